// round 4
// baseline (speedup 1.0000x reference)
#include <cuda_runtime.h>
#include <math.h>

#define N_INST 16384
#define NB1    1024
#define NB2    64
#define DIM    1024
#define NATT   256
#define NCLS   512

typedef unsigned long long u64;

// ---------------- packed f32x2 helpers (sm_100+) ---------------------------
__device__ __forceinline__ u64 pack_dup(float s) {
    u64 d; asm("mov.b64 %0, {%1, %1};" : "=l"(d) : "f"(s)); return d;
}
__device__ __forceinline__ u64 pack2(float a, float b) {
    u64 d; asm("mov.b64 %0, {%1, %2};" : "=l"(d) : "f"(a), "f"(b)); return d;
}
__device__ __forceinline__ void unpack2(u64 v, float& lo, float& hi) {
    asm("mov.b64 {%0, %1}, %2;" : "=f"(lo), "=f"(hi) : "l"(v));
}
__device__ __forceinline__ void ffma2(u64& acc, u64 a, u64 b) {
    asm("fma.rn.f32x2 %0, %1, %2, %0;" : "+l"(acc) : "l"(a), "l"(b));
}

// ---------------- scratch (device globals; no allocation allowed) ----------
__device__ float g_emb1[N_INST * DIM];   // 64 MB
__device__ float g_emb2[NB1 * DIM];      // 4 MB
__device__ float g_emb3[NB2 * DIM];
__device__ float g_s[N_INST + NB1 + NB2];
__device__ float g_stats[8];             // [max,sum] per level

__device__ __forceinline__ float* emb_buf(int lvl) {
    return lvl == 0 ? g_emb1 : (lvl == 1 ? g_emb2 : g_emb3);
}
__device__ __forceinline__ float* s_buf(int lvl) {
    return lvl == 0 ? g_s : (lvl == 1 ? g_s + N_INST : g_s + N_INST + NB1);
}

// ---------------------------------------------------------------------------
// Kernel 1: fused conv1+relu+pool -> conv2+relu+pool, one CTA per image.
//   conv1: 28x28x1 ->(5x5)-> 24x24x32 -> pool2 -> 12x12x32 (smem, stride-33)
//   conv2: 12x12x32 ->(5x5)-> 8x8x64 -> pool2 -> 4x4x64 = emb1 row (1024)
// All inner products use fma.rn.f32x2 (2 fp32 MACs / issue slot).
// ---------------------------------------------------------------------------
#define P1_STRIDE 33

__global__ __launch_bounds__(256) void fused_conv_kernel(
    const float* __restrict__ x,
    const float* __restrict__ w1, const float* __restrict__ b1,
    const float* __restrict__ w2, const float* __restrict__ b2)
{
    __shared__ __align__(16) float p1[144 * P1_STRIDE];  // conv1 pooled out; later reused as exchange
    __shared__ __align__(16) float smu[6464];            // A: in(784)+w1(800)+b1(32) | B: w2 chunk(6400)+b2(64)

    const int tid = threadIdx.x;
    const int n   = blockIdx.x;

    // ---------------- Phase A: conv1 + relu + maxpool into smem ----------------
    {
        float* in_s = smu;          // 784
        float* w1_s = smu + 784;    // 800 (16B-aligned: 784*4=3136 ✓)
        float* b1_s = smu + 1584;   // 32
        const float* xin = x + n * 784;
        for (int i = tid; i < 784; i += 256) in_s[i] = xin[i];
        for (int i = tid; i < 800; i += 256) w1_s[i] = w1[i];
        if (tid < 32) b1_s[tid] = b1[tid];
        __syncthreads();

        // 144 pooled positions x 8 chgroups(of 4) = 1152 tasks
        for (int t = tid; t < 1152; t += 256) {
            const int c0 = (t & 7) * 4;
            const int p  = t >> 3;
            const int pr = p / 12, pc = p % 12;
            const int y0 = pr * 2, x0 = pc * 2;

            u64 acc[2][4];                   // [ch-pair][pool-j]
            #pragma unroll
            for (int i = 0; i < 2; i++)
                #pragma unroll
                for (int j = 0; j < 4; j++) acc[i][j] = 0ull;

            for (int ky = 0; ky < 5; ky++) {
                #pragma unroll
                for (int kx = 0; kx < 5; kx++) {
                    const ulonglong2 wv = *(const ulonglong2*)&w1_s[(ky * 5 + kx) * 32 + c0];
                    #pragma unroll
                    for (int j = 0; j < 4; j++) {
                        const int dy = j >> 1, dx = j & 1;
                        const u64 iv = pack_dup(in_s[(y0 + dy + ky) * 28 + (x0 + dx + kx)]);
                        ffma2(acc[0][j], wv.x, iv);
                        ffma2(acc[1][j], wv.y, iv);
                    }
                }
            }
            #pragma unroll
            for (int i = 0; i < 2; i++) {
                float a0, a1, b0v, b1v, cc0, cc1, d0, d1;
                unpack2(acc[i][0], a0, a1);
                unpack2(acc[i][1], b0v, b1v);
                unpack2(acc[i][2], cc0, cc1);
                unpack2(acc[i][3], d0, d1);
                const float mlo = fmaxf(fmaxf(a0, b0v), fmaxf(cc0, d0));
                const float mhi = fmaxf(fmaxf(a1, b1v), fmaxf(cc1, d1));
                p1[p * P1_STRIDE + c0 + 2 * i]     = fmaxf(mlo + b1_s[c0 + 2 * i], 0.f);
                p1[p * P1_STRIDE + c0 + 2 * i + 1] = fmaxf(mhi + b1_s[c0 + 2 * i + 1], 0.f);
            }
        }
    }
    __syncthreads();

    // ---------------- Phase B: conv2 + relu + maxpool -> emb1 ----------------
    {
        float* w2_s = smu;          // 6400 per ci-chunk: [(ky*5+kx)*256 + cil*64 + c]
        float* b2_s = smu + 6400;   // 64

        const int chgrp = tid & 7;           // 8 groups x 8 out-channels
        const int half  = (tid >> 3) & 1;    // dy of pool window
        const int p     = tid >> 4;          // pooled position 0..15
        const int c0 = chgrp * 8;
        const int pr = p >> 2, pc = p & 3;
        const int oy = pr * 2 + half;        // conv-output row handled by this thread
        const int ox = pc * 2;               // dx in {0,1} -> acc[.][dx]

        u64 acc[4][2];                       // [ch-pair][dx]
        #pragma unroll
        for (int i = 0; i < 4; i++) { acc[i][0] = 0ull; acc[i][1] = 0ull; }

        for (int cc = 0; cc < 8; cc++) {     // 8 chunks of 4 input channels
            __syncthreads();                 // previous chunk consumed
            {   // load 6400 floats = 1600 float4, coalesced
                const float4* src = (const float4*)w2;
                float4* dst = (float4*)w2_s;
                for (int i = tid; i < 1600; i += 256) {
                    const int q = i >> 6;        // ky*5+kx
                    const int r = i & 63;        // within 256-float block /4
                    dst[i] = src[q * 512 + cc * 64 + r];
                }
            }
            if (cc == 0 && tid < 64) b2_s[tid] = b2[tid];
            __syncthreads();

            for (int ky = 0; ky < 5; ky++) {
                const int row = (oy + ky) * 12;
                #pragma unroll
                for (int kx = 0; kx < 5; kx++) {
                    #pragma unroll
                    for (int cil = 0; cil < 4; cil++) {
                        const int ci = cc * 4 + cil;
                        const int ibase = (row + ox + kx) * P1_STRIDE + ci;
                        const u64 d0 = pack_dup(p1[ibase]);
                        const u64 d1 = pack_dup(p1[ibase + P1_STRIDE]);
                        const int wb = (ky * 5 + kx) * 256 + cil * 64 + c0;
                        const ulonglong2 wA = *(const ulonglong2*)&w2_s[wb];
                        const ulonglong2 wB = *(const ulonglong2*)&w2_s[wb + 4];
                        ffma2(acc[0][0], wA.x, d0);
                        ffma2(acc[1][0], wA.y, d0);
                        ffma2(acc[2][0], wB.x, d0);
                        ffma2(acc[3][0], wB.y, d0);
                        ffma2(acc[0][1], wA.x, d1);
                        ffma2(acc[1][1], wA.y, d1);
                        ffma2(acc[2][1], wB.x, d1);
                        ffma2(acc[3][1], wB.y, d1);
                    }
                }
            }
        }

        // pool over dx within thread, then over dy across partner threads via smem
        float mx[8];
        #pragma unroll
        for (int i = 0; i < 4; i++) {
            float a0, a1, b0v, b1v;
            unpack2(acc[i][0], a0, a1);
            unpack2(acc[i][1], b0v, b1v);
            mx[2 * i]     = fmaxf(a0, b0v);
            mx[2 * i + 1] = fmaxf(a1, b1v);
        }
        __syncthreads();                     // p1 dead -> reuse as exchange
        float* exch = p1;
        #pragma unroll
        for (int k = 0; k < 8; k++) exch[tid * 8 + k] = mx[k];
        __syncthreads();

        if (half == 0) {
            const float* other = &exch[(tid + 8) * 8];
            float4 oA, oB;
            float* oa = &oA.x; float* ob = &oB.x;
            #pragma unroll
            for (int k = 0; k < 4; k++)
                oa[k] = fmaxf(fmaxf(mx[k], other[k]) + b2_s[c0 + k], 0.f);
            #pragma unroll
            for (int k = 0; k < 4; k++)
                ob[k] = fmaxf(fmaxf(mx[k + 4], other[k + 4]) + b2_s[c0 + k + 4], 0.f);
            float* dst = &g_emb1[(long)n * DIM + p * 64 + c0];
            *(float4*)dst = oA;
            *(float4*)(dst + 4) = oB;
        }
    }
}

// ---------------------------------------------------------------------------
// Kernel 2: attention scores s_i = sigmoid(tanh(emb_i @ W + b) @ v + vb)
// 8 rows per CTA staged in smem; 256 threads = 256 attention units; f32x2 FMA.
// ---------------------------------------------------------------------------
__global__ __launch_bounds__(256) void att_kernel(
    int lvl, const float* __restrict__ W, const float* __restrict__ b,
    const float* __restrict__ v, const float* __restrict__ vb)
{
    __shared__ __align__(16) float es[8 * DIM];
    __shared__ float wred[8][8];

    const float* emb   = emb_buf(lvl);
    float*       s_out = s_buf(lvl);
    const int tid  = threadIdx.x;
    const int row0 = blockIdx.x * 8;

    const float* src = emb + (long)row0 * DIM;
    for (int i = tid; i < 8 * DIM; i += 256) es[i] = src[i];
    __syncthreads();

    u64 acc[8];
    #pragma unroll
    for (int r = 0; r < 8; r++) acc[r] = 0ull;

    const float* Wp = W + tid;
    for (int k = 0; k < DIM; k += 4) {
        const float wv0 = Wp[(k + 0) * NATT];
        const float wv1 = Wp[(k + 1) * NATT];
        const float wv2 = Wp[(k + 2) * NATT];
        const float wv3 = Wp[(k + 3) * NATT];
        const u64 w01 = pack2(wv0, wv1);
        const u64 w23 = pack2(wv2, wv3);
        #pragma unroll
        for (int r = 0; r < 8; r++) {
            const ulonglong2 e = *(const ulonglong2*)&es[r * DIM + k];
            ffma2(acc[r], e.x, w01);
            ffma2(acc[r], e.y, w23);
        }
    }

    const float bj = b[tid], vj = v[tid];
    const int lane = tid & 31, wrp = tid >> 5;
    #pragma unroll
    for (int r = 0; r < 8; r++) {
        float lo, hi;
        unpack2(acc[r], lo, hi);
        float pv = tanhf(lo + hi + bj) * vj;
        #pragma unroll
        for (int off = 16; off; off >>= 1) pv += __shfl_xor_sync(0xffffffffu, pv, off);
        if (lane == 0) wred[wrp][r] = pv;
    }
    __syncthreads();
    if (tid < 8) {
        float z = 0.f;
        #pragma unroll
        for (int w = 0; w < 8; w++) z += wred[w][tid];
        z += vb[0];
        s_out[row0 + tid] = 1.f / (1.f + expf(-z));
    }
}

// ---------------------------------------------------------------------------
// Kernel 3: global softmax stats (max, sum of exp)
// ---------------------------------------------------------------------------
__global__ __launch_bounds__(1024) void stats_kernel(int lvl, int R)
{
    __shared__ float red[1024];
    const float* s = s_buf(lvl);
    const int tid = threadIdx.x;

    float m = -1e30f;
    for (int i = tid; i < R; i += 1024) m = fmaxf(m, s[i]);
    red[tid] = m; __syncthreads();
    for (int off = 512; off; off >>= 1) {
        if (tid < off) red[tid] = fmaxf(red[tid], red[tid + off]);
        __syncthreads();
    }
    const float mx = red[0];
    __syncthreads();

    float sum = 0.f;
    for (int i = tid; i < R; i += 1024) sum += expf(s[i] - mx);
    red[tid] = sum; __syncthreads();
    for (int off = 512; off; off >>= 1) {
        if (tid < off) red[tid] += red[tid + off];
        __syncthreads();
    }
    if (tid == 0) { g_stats[lvl * 2] = mx; g_stats[lvl * 2 + 1] = red[0]; }
}

// ---------------------------------------------------------------------------
// Kernel 4: softmax-weighted segment sum (16 contiguous rows per bag), float4
// ---------------------------------------------------------------------------
__global__ __launch_bounds__(256) void segsum_kernel(int lvl)
{
    __shared__ float ws[16];
    const float* ein  = emb_buf(lvl);
    float*       eout = emb_buf(lvl + 1);
    const float* s    = s_buf(lvl);
    const int bg = blockIdx.x, tid = threadIdx.x;

    if (tid < 16) {
        const float mx = g_stats[lvl * 2];
        const float inv = 1.f / g_stats[lvl * 2 + 1];
        ws[tid] = expf(s[bg * 16 + tid] - mx) * inv;
    }
    __syncthreads();

    const float4* base = (const float4*)(ein + (long)bg * 16 * DIM);
    float4* dst = (float4*)(eout + (long)bg * DIM);
    for (int d = tid; d < DIM / 4; d += 256) {
        float4 a = make_float4(0.f, 0.f, 0.f, 0.f);
        #pragma unroll
        for (int i = 0; i < 16; i++) {
            const float w = ws[i];
            const float4 e = base[i * (DIM / 4) + d];
            a.x += w * e.x; a.y += w * e.y; a.z += w * e.z; a.w += w * e.w;
        }
        dst[d] = a;
    }
}

// ---------------------------------------------------------------------------
// Kernel 5: level-3 softmax + outer pooling + classifier + sigmoid
// ---------------------------------------------------------------------------
__global__ __launch_bounds__(512) void final_kernel(
    const float* __restrict__ clsW, const float* __restrict__ clsb,
    const float* __restrict__ outW, const float* __restrict__ outb,
    float* __restrict__ out)
{
    __shared__ float w3[64];
    __shared__ float outer[DIM];
    __shared__ float red[512];
    const int tid = threadIdx.x;
    const float* s3 = s_buf(2);

    if (tid == 0) {
        float mx = -1e30f;
        for (int i = 0; i < 64; i++) mx = fmaxf(mx, s3[i]);
        float sum = 0.f;
        for (int i = 0; i < 64; i++) { float e = expf(s3[i] - mx); w3[i] = e; sum += e; }
        const float inv = 1.f / sum;
        for (int i = 0; i < 64; i++) w3[i] *= inv;
    }
    __syncthreads();

    for (int d = tid; d < DIM; d += 512) {
        float acc = 0.f;
        #pragma unroll 8
        for (int b2 = 0; b2 < 64; b2++) acc += w3[b2] * g_emb3[b2 * DIM + d];
        outer[d] = acc;
    }
    __syncthreads();

    float acc = 0.f;
    const float* wp = clsW + tid;
    for (int d = 0; d < DIM; d++) acc += outer[d] * wp[d * NCLS];
    red[tid] = (acc + clsb[tid]) * outW[tid];
    __syncthreads();
    for (int off = 256; off; off >>= 1) {
        if (tid < off) red[tid] += red[tid + off];
        __syncthreads();
    }
    if (tid == 0) out[0] = 1.f / (1.f + expf(-(red[0] + outb[0])));
}

// ---------------------------------------------------------------------------
extern "C" void kernel_launch(void* const* d_in, const int* in_sizes, int n_in,
                              void* d_out, int out_size)
{
    const float* x    = (const float*)d_in[0];
    const float* c1w  = (const float*)d_in[1];
    const float* c1b  = (const float*)d_in[2];
    const float* c2w  = (const float*)d_in[3];
    const float* c2b  = (const float*)d_in[4];
    const float* a1W  = (const float*)d_in[5];
    const float* a1b  = (const float*)d_in[6];
    const float* a1v  = (const float*)d_in[7];
    const float* a1vb = (const float*)d_in[8];
    const float* a2W  = (const float*)d_in[9];
    const float* a2b  = (const float*)d_in[10];
    const float* a2v  = (const float*)d_in[11];
    const float* a2vb = (const float*)d_in[12];
    const float* a3W  = (const float*)d_in[13];
    const float* a3b  = (const float*)d_in[14];
    const float* a3v  = (const float*)d_in[15];
    const float* a3vb = (const float*)d_in[16];
    const float* clsW = (const float*)d_in[17];
    const float* clsb = (const float*)d_in[18];
    const float* outW = (const float*)d_in[19];
    const float* outb = (const float*)d_in[20];

    fused_conv_kernel<<<N_INST, 256>>>(x, c1w, c1b, c2w, c2b);

    att_kernel<<<N_INST / 8, 256>>>(0, a1W, a1b, a1v, a1vb);
    stats_kernel<<<1, 1024>>>(0, N_INST);
    segsum_kernel<<<NB1, 256>>>(0);

    att_kernel<<<NB1 / 8, 256>>>(1, a2W, a2b, a2v, a2vb);
    stats_kernel<<<1, 1024>>>(1, NB1);
    segsum_kernel<<<NB2, 256>>>(1);

    att_kernel<<<NB2 / 8, 256>>>(2, a3W, a3b, a3v, a3vb);
    final_kernel<<<1, 512>>>(clsW, clsb, outW, outb, (float*)d_out);
}

// round 5
// speedup vs baseline: 3.6445x; 3.6445x over previous
#include <cuda_runtime.h>
#include <cuda_bf16.h>
#include <math.h>

#define N_INST 16384
#define NB1    1024
#define NB2    64
#define DIM    1024
#define NATT   256
#define NCLS   512

// ---------------- scratch (device globals; no allocation allowed) ----------
__device__ float g_emb1[N_INST * DIM];   // 64 MB
__device__ float g_emb2[NB1 * DIM];
__device__ float g_emb3[NB2 * DIM];
__device__ float g_s[N_INST + NB1 + NB2];
__device__ float g_stats[8];
// conv2 weights, transposed [n=64][k=800], split into bf16 hi/lo
__device__ __nv_bfloat16 g_w2t_hi[64 * 800];
__device__ __nv_bfloat16 g_w2t_lo[64 * 800];

__device__ __forceinline__ float* emb_buf(int lvl) {
    return lvl == 0 ? g_emb1 : (lvl == 1 ? g_emb2 : g_emb3);
}
__device__ __forceinline__ float* s_buf(int lvl) {
    return lvl == 0 ? g_s : (lvl == 1 ? g_s + N_INST : g_s + N_INST + NB1);
}

// ---------------- mma helpers ----------------------------------------------
__device__ __forceinline__ void ldsm4(unsigned& r0, unsigned& r1, unsigned& r2,
                                      unsigned& r3, unsigned a) {
    asm volatile("ldmatrix.sync.aligned.m8n8.x4.shared.b16 {%0,%1,%2,%3}, [%4];"
                 : "=r"(r0), "=r"(r1), "=r"(r2), "=r"(r3) : "r"(a));
}
__device__ __forceinline__ void mma_bf16(float* c, unsigned a0, unsigned a1,
                                         unsigned a2, unsigned a3,
                                         unsigned b0, unsigned b1) {
    asm volatile(
        "mma.sync.aligned.m16n8k16.row.col.f32.bf16.bf16.f32 "
        "{%0,%1,%2,%3},{%4,%5,%6,%7},{%8,%9},{%0,%1,%2,%3};"
        : "+f"(c[0]), "+f"(c[1]), "+f"(c[2]), "+f"(c[3])
        : "r"(a0), "r"(a1), "r"(a2), "r"(a3), "r"(b0), "r"(b1));
}

// ---------------------------------------------------------------------------
// Prep: transpose conv2 weights [800][64] -> [64][800], split bf16 hi/lo
// ---------------------------------------------------------------------------
__global__ __launch_bounds__(256) void prep_w2t(const float* __restrict__ w2) {
    const int idx = blockIdx.x * 256 + threadIdx.x;
    if (idx >= 64 * 800) return;
    const int n = idx / 800, k = idx - n * 800;
    const float v = w2[k * 64 + n];
    const __nv_bfloat16 h = __float2bfloat16(v);
    g_w2t_hi[idx] = h;
    g_w2t_lo[idx] = __float2bfloat16(v - __bfloat162float(h));
}

// ---------------------------------------------------------------------------
// Fused conv kernel: one CTA = 2 images.
//  Phase A (scalar fp32): conv1 5x5 + relu + pool -> 12x12x32, stored in smem
//    as bf16 hi/lo planes, row stride 40 elems (80B, conflict-free ldmatrix).
//  Phase B (tensor): conv2 as implicit GEMM C[128,64] = A[128,800] x B[800,64]
//    via mma.m16n8k16 bf16, 3-term hi/lo split for fp32-grade accuracy.
//    Epilogue: 2x2 maxpool + bias + relu -> g_emb1.
// smem layout (bytes): p1h[2 img][144*40 bf16] @0 (23040)
//                      p1l @23040 (23040)
//                      B slabs / phaseA staging @46080 (43008) -> total 89088
// ---------------------------------------------------------------------------
#define FC_SMEM 89088

__global__ __launch_bounds__(256) void fused_conv_kernel(
    const float* __restrict__ x,
    const float* __restrict__ w1, const float* __restrict__ b1,
    const float* __restrict__ b2)
{
    extern __shared__ char smem[];
    const unsigned sbase = (unsigned)__cvta_generic_to_shared(smem);
    const int tid = threadIdx.x;

    __nv_bfloat16* p1h = (__nv_bfloat16*)smem;             // [img][144*40]
    __nv_bfloat16* p1l = (__nv_bfloat16*)(smem + 23040);

    // ---------------- Phase A: conv1 + relu + pool (scalar fp32) ----------
    {
        float* stg  = (float*)(smem + 46080);
        float* w1_s = stg;          // 800
        float* b1_s = stg + 800;    // 32
        float* in_s = stg + 832;    // 2 x 784
        for (int i = tid; i < 800; i += 256) w1_s[i] = w1[i];
        if (tid < 32) b1_s[tid] = b1[tid];
        const float* x0 = x + (size_t)blockIdx.x * 2 * 784;
        for (int i = tid; i < 1568; i += 256) in_s[i] = x0[i];
        __syncthreads();

        for (int t = tid; t < 2304; t += 256) {
            const int img = t >= 1152;
            const int tt  = t - img * 1152;
            const float* in = in_s + img * 784;
            const int c0 = (tt & 7) * 4;
            const int p  = tt >> 3;
            const int pr = p / 12, pc = p % 12;
            const int y0 = pr * 2, xx0 = pc * 2;
            float acc[4][4];
            #pragma unroll
            for (int j = 0; j < 4; j++)
                #pragma unroll
                for (int ch = 0; ch < 4; ch++) acc[j][ch] = 0.f;

            for (int ky = 0; ky < 5; ky++) {
                #pragma unroll
                for (int kx = 0; kx < 5; kx++) {
                    const float4 wv = *(const float4*)&w1_s[(ky * 5 + kx) * 32 + c0];
                    #pragma unroll
                    for (int j = 0; j < 4; j++) {
                        const int dy = j >> 1, dx = j & 1;
                        const float iv = in[(y0 + dy + ky) * 28 + (xx0 + dx + kx)];
                        acc[j][0] += iv * wv.x; acc[j][1] += iv * wv.y;
                        acc[j][2] += iv * wv.z; acc[j][3] += iv * wv.w;
                    }
                }
            }
            __nv_bfloat16* ph = p1h + img * 5760 + p * 40 + c0;
            __nv_bfloat16* pl = p1l + img * 5760 + p * 40 + c0;
            #pragma unroll
            for (int ch = 0; ch < 4; ch++) {
                float m = fmaxf(fmaxf(acc[0][ch], acc[1][ch]),
                                fmaxf(acc[2][ch], acc[3][ch]));
                const float v = fmaxf(m + b1_s[c0 + ch], 0.f);
                const __nv_bfloat16 h = __float2bfloat16(v);
                ph[ch] = h;
                pl[ch] = __float2bfloat16(v - __bfloat162float(h));
            }
        }
    }

    // ---------------- Phase B: conv2 via bf16 tensor-core GEMM ------------
    {
        const int l   = tid & 31;
        const int w   = tid >> 5;
        const int mt  = w & 3;        // m-tile within image (16 rows each)
        const int img = w >> 2;       // image within CTA

        const int lane_r = ((l >> 3) & 1) * 8 + (l & 7);   // A row within tile
        const int pos = mt * 16 + lane_r;                  // conv-output pos 0..63
        const int my = pos >> 3, mx = pos & 7;
        const unsigned khalf = ((l >> 4) & 1) * 16;        // +8 elems for k8-15

        const unsigned aH = sbase + img * 11520;
        const unsigned aL = sbase + 23040 + img * 11520;
        const unsigned BH = sbase + 46080;           // hi slab [64][168 bf16]
        const unsigned BL = BH + 21504;              // lo slab

        float acc[8][4];
        #pragma unroll
        for (int j = 0; j < 8; j++)
            #pragma unroll
            for (int q = 0; q < 4; q++) acc[j][q] = 0.f;

        const char* wth = (const char*)g_w2t_hi;
        const char* wtl = (const char*)g_w2t_lo;

        for (int ky = 0; ky < 5; ky++) {
            __syncthreads();   // previous slab (or phase-A staging) consumed
            // load B slabs: rows n=0..63, 160 bf16 each (20 uint4), hi + lo
            for (int i = tid; i < 2560; i += 256) {
                const int s  = i >= 1280;
                const int ii = i - s * 1280;
                const int n  = ii / 20, c = ii - n * 20;
                const char* src = (s ? wtl : wth) + n * 1600 + ky * 320 + c * 16;
                char* dst = smem + 46080 + s * 21504 + n * 336 + c * 16;
                *(uint4*)dst = *(const uint4*)src;
            }
            __syncthreads();

            const unsigned arow = ((my + ky) * 12 + mx) * 80;
            for (int kx = 0; kx < 5; kx++) {
                const unsigned ao = arow + kx * 80 + khalf;
                #pragma unroll
                for (int hf = 0; hf < 2; hf++) {
                    const unsigned ab = ao + hf * 32;
                    unsigned ah0, ah1, ah2, ah3, al0, al1, al2, al3;
                    ldsm4(ah0, ah1, ah2, ah3, aH + ab);
                    ldsm4(al0, al1, al2, al3, aL + ab);

                    const unsigned kb = (unsigned)(kx * 2 + hf) * 32;
                    unsigned bh[16], bl[16];
                    ldsm4(bh[0],  bh[1],  bh[2],  bh[3],  BH + l * 336 + kb);
                    ldsm4(bh[4],  bh[5],  bh[6],  bh[7],  BH + (l + 32) * 336 + kb);
                    ldsm4(bh[8],  bh[9],  bh[10], bh[11], BH + l * 336 + kb + 16);
                    ldsm4(bh[12], bh[13], bh[14], bh[15], BH + (l + 32) * 336 + kb + 16);
                    ldsm4(bl[0],  bl[1],  bl[2],  bl[3],  BL + l * 336 + kb);
                    ldsm4(bl[4],  bl[5],  bl[6],  bl[7],  BL + (l + 32) * 336 + kb);
                    ldsm4(bl[8],  bl[9],  bl[10], bl[11], BL + l * 336 + kb + 16);
                    ldsm4(bl[12], bl[13], bl[14], bl[15], BL + (l + 32) * 336 + kb + 16);

                    #pragma unroll
                    for (int j = 0; j < 8; j++) {
                        mma_bf16(acc[j], ah0, ah1, ah2, ah3, bh[j], bh[8 + j]);
                        mma_bf16(acc[j], ah0, ah1, ah2, ah3, bl[j], bl[8 + j]);
                        mma_bf16(acc[j], al0, al1, al2, al3, bh[j], bh[8 + j]);
                    }
                }
            }
        }

        // epilogue: 2x2 maxpool + bias + relu -> emb1
        // fragment row r = l/4 (rows r & r+8 in-lane), cols n = j*8 + 2*(l&3)
        const long row_img = (long)blockIdx.x * 2 + img;
        #pragma unroll
        for (int j = 0; j < 8; j++) {
            float v0 = fmaxf(acc[j][0], acc[j][2]);   // col n
            float v1 = fmaxf(acc[j][1], acc[j][3]);   // col n+1
            const float u0 = fmaxf(v0, __shfl_down_sync(0xffffffffu, v0, 4));
            const float u1 = fmaxf(v1, __shfl_down_sync(0xffffffffu, v1, 4));
            if (((l >> 2) & 1) == 0) {
                const int pc = l >> 3;                // pooled col 0..3
                const int p  = mt * 4 + pc;           // pooled pos (pr = mt)
                const int nn = j * 8 + 2 * (l & 3);
                float2 o;
                o.x = fmaxf(u0 + b2[nn], 0.f);
                o.y = fmaxf(u1 + b2[nn + 1], 0.f);
                *(float2*)&g_emb1[row_img * DIM + p * 64 + nn] = o;
            }
        }
    }
}

// ---------------------------------------------------------------------------
// Attention scores s_i = sigmoid(tanh(emb_i @ W + b) @ v + vb)  (scalar fp32)
// ---------------------------------------------------------------------------
__global__ __launch_bounds__(256) void att_kernel(
    int lvl, const float* __restrict__ W, const float* __restrict__ b,
    const float* __restrict__ v, const float* __restrict__ vb)
{
    __shared__ __align__(16) float es[8 * DIM];
    __shared__ float wred[8][8];

    const float* emb   = emb_buf(lvl);
    float*       s_out = s_buf(lvl);
    const int tid  = threadIdx.x;
    const int row0 = blockIdx.x * 8;

    const float* src = emb + (long)row0 * DIM;
    for (int i = tid; i < 8 * DIM; i += 256) es[i] = src[i];
    __syncthreads();

    float acc[8] = {0.f, 0.f, 0.f, 0.f, 0.f, 0.f, 0.f, 0.f};
    const float* Wp = W + tid;
    for (int k = 0; k < DIM; k += 4) {
        const float wv0 = Wp[(k + 0) * NATT];
        const float wv1 = Wp[(k + 1) * NATT];
        const float wv2 = Wp[(k + 2) * NATT];
        const float wv3 = Wp[(k + 3) * NATT];
        #pragma unroll
        for (int r = 0; r < 8; r++) {
            const float4 e = *(const float4*)&es[r * DIM + k];
            acc[r] += e.x * wv0;
            acc[r] += e.y * wv1;
            acc[r] += e.z * wv2;
            acc[r] += e.w * wv3;
        }
    }

    const float bj = b[tid], vj = v[tid];
    const int lane = tid & 31, wrp = tid >> 5;
    #pragma unroll
    for (int r = 0; r < 8; r++) {
        float pv = tanhf(acc[r] + bj) * vj;
        #pragma unroll
        for (int off = 16; off; off >>= 1) pv += __shfl_xor_sync(0xffffffffu, pv, off);
        if (lane == 0) wred[wrp][r] = pv;
    }
    __syncthreads();
    if (tid < 8) {
        float z = 0.f;
        #pragma unroll
        for (int w = 0; w < 8; w++) z += wred[w][tid];
        z += vb[0];
        s_out[row0 + tid] = 1.f / (1.f + expf(-z));
    }
}

// ---------------------------------------------------------------------------
__global__ __launch_bounds__(1024) void stats_kernel(int lvl, int R)
{
    __shared__ float red[1024];
    const float* s = s_buf(lvl);
    const int tid = threadIdx.x;

    float m = -1e30f;
    for (int i = tid; i < R; i += 1024) m = fmaxf(m, s[i]);
    red[tid] = m; __syncthreads();
    for (int off = 512; off; off >>= 1) {
        if (tid < off) red[tid] = fmaxf(red[tid], red[tid + off]);
        __syncthreads();
    }
    const float mx = red[0];
    __syncthreads();

    float sum = 0.f;
    for (int i = tid; i < R; i += 1024) sum += expf(s[i] - mx);
    red[tid] = sum; __syncthreads();
    for (int off = 512; off; off >>= 1) {
        if (tid < off) red[tid] += red[tid + off];
        __syncthreads();
    }
    if (tid == 0) { g_stats[lvl * 2] = mx; g_stats[lvl * 2 + 1] = red[0]; }
}

// ---------------------------------------------------------------------------
__global__ __launch_bounds__(256) void segsum_kernel(int lvl)
{
    __shared__ float ws[16];
    const float* ein  = emb_buf(lvl);
    float*       eout = emb_buf(lvl + 1);
    const float* s    = s_buf(lvl);
    const int bg = blockIdx.x, tid = threadIdx.x;

    if (tid < 16) {
        const float mx = g_stats[lvl * 2];
        const float inv = 1.f / g_stats[lvl * 2 + 1];
        ws[tid] = expf(s[bg * 16 + tid] - mx) * inv;
    }
    __syncthreads();

    const float4* base = (const float4*)(ein + (long)bg * 16 * DIM);
    float4* dst = (float4*)(eout + (long)bg * DIM);
    for (int d = tid; d < DIM / 4; d += 256) {
        float4 a = make_float4(0.f, 0.f, 0.f, 0.f);
        #pragma unroll
        for (int i = 0; i < 16; i++) {
            const float w = ws[i];
            const float4 e = base[i * (DIM / 4) + d];
            a.x += w * e.x; a.y += w * e.y; a.z += w * e.z; a.w += w * e.w;
        }
        dst[d] = a;
    }
}

// ---------------------------------------------------------------------------
__global__ __launch_bounds__(512) void final_kernel(
    const float* __restrict__ clsW, const float* __restrict__ clsb,
    const float* __restrict__ outW, const float* __restrict__ outb,
    float* __restrict__ out)
{
    __shared__ float w3[64];
    __shared__ float outer[DIM];
    __shared__ float red[512];
    const int tid = threadIdx.x;
    const float* s3 = s_buf(2);

    if (tid == 0) {
        float mx = -1e30f;
        for (int i = 0; i < 64; i++) mx = fmaxf(mx, s3[i]);
        float sum = 0.f;
        for (int i = 0; i < 64; i++) { float e = expf(s3[i] - mx); w3[i] = e; sum += e; }
        const float inv = 1.f / sum;
        for (int i = 0; i < 64; i++) w3[i] *= inv;
    }
    __syncthreads();

    for (int d = tid; d < DIM; d += 512) {
        float acc = 0.f;
        #pragma unroll 8
        for (int b2 = 0; b2 < 64; b2++) acc += w3[b2] * g_emb3[b2 * DIM + d];
        outer[d] = acc;
    }
    __syncthreads();

    float acc = 0.f;
    const float* wp = clsW + tid;
    for (int d = 0; d < DIM; d++) acc += outer[d] * wp[d * NCLS];
    red[tid] = (acc + clsb[tid]) * outW[tid];
    __syncthreads();
    for (int off = 256; off; off >>= 1) {
        if (tid < off) red[tid] += red[tid + off];
        __syncthreads();
    }
    if (tid == 0) out[0] = 1.f / (1.f + expf(-(red[0] + outb[0])));
}

// ---------------------------------------------------------------------------
extern "C" void kernel_launch(void* const* d_in, const int* in_sizes, int n_in,
                              void* d_out, int out_size)
{
    const float* x    = (const float*)d_in[0];
    const float* c1w  = (const float*)d_in[1];
    const float* c1b  = (const float*)d_in[2];
    const float* c2w  = (const float*)d_in[3];
    const float* c2b  = (const float*)d_in[4];
    const float* a1W  = (const float*)d_in[5];
    const float* a1b  = (const float*)d_in[6];
    const float* a1v  = (const float*)d_in[7];
    const float* a1vb = (const float*)d_in[8];
    const float* a2W  = (const float*)d_in[9];
    const float* a2b  = (const float*)d_in[10];
    const float* a2v  = (const float*)d_in[11];
    const float* a2vb = (const float*)d_in[12];
    const float* a3W  = (const float*)d_in[13];
    const float* a3b  = (const float*)d_in[14];
    const float* a3v  = (const float*)d_in[15];
    const float* a3vb = (const float*)d_in[16];
    const float* clsW = (const float*)d_in[17];
    const float* clsb = (const float*)d_in[18];
    const float* outW = (const float*)d_in[19];
    const float* outb = (const float*)d_in[20];

    cudaFuncSetAttribute(fused_conv_kernel,
                         cudaFuncAttributeMaxDynamicSharedMemorySize, FC_SMEM);

    prep_w2t<<<200, 256>>>(c2w);
    fused_conv_kernel<<<N_INST / 2, 256, FC_SMEM>>>(x, c1w, c1b, c2b);

    att_kernel<<<N_INST / 8, 256>>>(0, a1W, a1b, a1v, a1vb);
    stats_kernel<<<1, 1024>>>(0, N_INST);
    segsum_kernel<<<NB1, 256>>>(0);

    att_kernel<<<NB1 / 8, 256>>>(1, a2W, a2b, a2v, a2vb);
    stats_kernel<<<1, 1024>>>(1, NB1);
    segsum_kernel<<<NB2, 256>>>(1);

    att_kernel<<<NB2 / 8, 256>>>(2, a3W, a3b, a3v, a3vb);
    final_kernel<<<1, 512>>>(clsW, clsb, outW, outb, (float*)d_out);
}

// round 6
// speedup vs baseline: 3.9946x; 1.0961x over previous
#include <cuda_runtime.h>
#include <cuda_bf16.h>
#include <math.h>

#define N_INST 16384
#define NB1    1024
#define NB2    64
#define DIM    1024
#define NATT   256
#define NCLS   512

// ---------------- scratch (device globals; no allocation allowed) ----------
__device__ float g_emb1[N_INST * DIM];   // 64 MB
__device__ float g_emb2[NB1 * DIM];
__device__ float g_emb3[NB2 * DIM];
__device__ float g_s[N_INST + NB1 + NB2];
__device__ float g_stats[8];
// conv2 weights, transposed [n=64][k=800], split into bf16 hi/lo
__device__ __nv_bfloat16 g_w2t_hi[64 * 800];
__device__ __nv_bfloat16 g_w2t_lo[64 * 800];
// embeddings as bf16 hi/lo (for tensor-core attention GEMMs)
__device__ __nv_bfloat16 g_emb1h[N_INST * DIM], g_emb1l[N_INST * DIM];
__device__ __nv_bfloat16 g_emb2h[NB1 * DIM],    g_emb2l[NB1 * DIM];
__device__ __nv_bfloat16 g_emb3h[NB2 * DIM],    g_emb3l[NB2 * DIM];
// attention weights, transposed [n=256][k=1024], hi/lo, 3 levels
__device__ __nv_bfloat16 g_awt_hi[3 * NATT * DIM];
__device__ __nv_bfloat16 g_awt_lo[3 * NATT * DIM];

__device__ __forceinline__ float* emb_buf(int lvl) {
    return lvl == 0 ? g_emb1 : (lvl == 1 ? g_emb2 : g_emb3);
}
__device__ __forceinline__ float* s_buf(int lvl) {
    return lvl == 0 ? g_s : (lvl == 1 ? g_s + N_INST : g_s + N_INST + NB1);
}

// ---------------- mma helpers ----------------------------------------------
__device__ __forceinline__ void ldsm4(unsigned& r0, unsigned& r1, unsigned& r2,
                                      unsigned& r3, unsigned a) {
    asm volatile("ldmatrix.sync.aligned.m8n8.x4.shared.b16 {%0,%1,%2,%3}, [%4];"
                 : "=r"(r0), "=r"(r1), "=r"(r2), "=r"(r3) : "r"(a));
}
__device__ __forceinline__ void mma_bf16(float* c, unsigned a0, unsigned a1,
                                         unsigned a2, unsigned a3,
                                         unsigned b0, unsigned b1) {
    asm volatile(
        "mma.sync.aligned.m16n8k16.row.col.f32.bf16.bf16.f32 "
        "{%0,%1,%2,%3},{%4,%5,%6,%7},{%8,%9},{%0,%1,%2,%3};"
        : "+f"(c[0]), "+f"(c[1]), "+f"(c[2]), "+f"(c[3])
        : "r"(a0), "r"(a1), "r"(a2), "r"(a3), "r"(b0), "r"(b1));
}

// ---------------------------------------------------------------------------
// Prep kernels: weight transposes + bf16 hi/lo splits
// ---------------------------------------------------------------------------
__global__ __launch_bounds__(256) void prep_w2t(const float* __restrict__ w2) {
    const int idx = blockIdx.x * 256 + threadIdx.x;
    if (idx >= 64 * 800) return;
    const int n = idx / 800, k = idx - n * 800;
    const float v = w2[k * 64 + n];
    const __nv_bfloat16 h = __float2bfloat16(v);
    g_w2t_hi[idx] = h;
    g_w2t_lo[idx] = __float2bfloat16(v - __bfloat162float(h));
}

__global__ __launch_bounds__(256) void prep_awt(const float* __restrict__ W, int set) {
    const int idx = blockIdx.x * 256 + threadIdx.x;   // 262144 total
    const int n = idx >> 10, k = idx & 1023;
    const float v = W[k * NATT + n];
    const __nv_bfloat16 h = __float2bfloat16(v);
    g_awt_hi[set * (NATT * DIM) + idx] = h;
    g_awt_lo[set * (NATT * DIM) + idx] = __float2bfloat16(v - __bfloat162float(h));
}

// ---------------------------------------------------------------------------
// Fused conv kernel: one CTA = 2 images (same as R5, plus bf16 hi/lo emb1 out)
// ---------------------------------------------------------------------------
#define FC_SMEM 89088

__global__ __launch_bounds__(256) void fused_conv_kernel(
    const float* __restrict__ x,
    const float* __restrict__ w1, const float* __restrict__ b1,
    const float* __restrict__ b2)
{
    extern __shared__ char smem[];
    const unsigned sbase = (unsigned)__cvta_generic_to_shared(smem);
    const int tid = threadIdx.x;

    __nv_bfloat16* p1h = (__nv_bfloat16*)smem;             // [img][144*40]
    __nv_bfloat16* p1l = (__nv_bfloat16*)(smem + 23040);

    // ---------------- Phase A: conv1 + relu + pool (scalar fp32) ----------
    {
        float* stg  = (float*)(smem + 46080);
        float* w1_s = stg;          // 800
        float* b1_s = stg + 800;    // 32
        float* in_s = stg + 832;    // 2 x 784
        for (int i = tid; i < 800; i += 256) w1_s[i] = w1[i];
        if (tid < 32) b1_s[tid] = b1[tid];
        const float* x0 = x + (size_t)blockIdx.x * 2 * 784;
        for (int i = tid; i < 1568; i += 256) in_s[i] = x0[i];
        __syncthreads();

        for (int t = tid; t < 2304; t += 256) {
            const int img = t >= 1152;
            const int tt  = t - img * 1152;
            const float* in = in_s + img * 784;
            const int c0 = (tt & 7) * 4;
            const int p  = tt >> 3;
            const int pr = p / 12, pc = p % 12;
            const int y0 = pr * 2, xx0 = pc * 2;
            float acc[4][4];
            #pragma unroll
            for (int j = 0; j < 4; j++)
                #pragma unroll
                for (int ch = 0; ch < 4; ch++) acc[j][ch] = 0.f;

            for (int ky = 0; ky < 5; ky++) {
                #pragma unroll
                for (int kx = 0; kx < 5; kx++) {
                    const float4 wv = *(const float4*)&w1_s[(ky * 5 + kx) * 32 + c0];
                    #pragma unroll
                    for (int j = 0; j < 4; j++) {
                        const int dy = j >> 1, dx = j & 1;
                        const float iv = in[(y0 + dy + ky) * 28 + (xx0 + dx + kx)];
                        acc[j][0] += iv * wv.x; acc[j][1] += iv * wv.y;
                        acc[j][2] += iv * wv.z; acc[j][3] += iv * wv.w;
                    }
                }
            }
            __nv_bfloat16* ph = p1h + img * 5760 + p * 40 + c0;
            __nv_bfloat16* pl = p1l + img * 5760 + p * 40 + c0;
            #pragma unroll
            for (int ch = 0; ch < 4; ch++) {
                float m = fmaxf(fmaxf(acc[0][ch], acc[1][ch]),
                                fmaxf(acc[2][ch], acc[3][ch]));
                const float v = fmaxf(m + b1_s[c0 + ch], 0.f);
                const __nv_bfloat16 h = __float2bfloat16(v);
                ph[ch] = h;
                pl[ch] = __float2bfloat16(v - __bfloat162float(h));
            }
        }
    }

    // ---------------- Phase B: conv2 via bf16 tensor-core GEMM ------------
    {
        const int l   = tid & 31;
        const int w   = tid >> 5;
        const int mt  = w & 3;
        const int img = w >> 2;

        const int lane_r = ((l >> 3) & 1) * 8 + (l & 7);
        const int pos = mt * 16 + lane_r;
        const int my = pos >> 3, mx = pos & 7;
        const unsigned khalf = ((l >> 4) & 1) * 16;

        const unsigned aH = sbase + img * 11520;
        const unsigned aL = sbase + 23040 + img * 11520;
        const unsigned BH = sbase + 46080;
        const unsigned BL = BH + 21504;

        float acc[8][4];
        #pragma unroll
        for (int j = 0; j < 8; j++)
            #pragma unroll
            for (int q = 0; q < 4; q++) acc[j][q] = 0.f;

        const char* wth = (const char*)g_w2t_hi;
        const char* wtl = (const char*)g_w2t_lo;

        for (int ky = 0; ky < 5; ky++) {
            __syncthreads();
            for (int i = tid; i < 2560; i += 256) {
                const int s  = i >= 1280;
                const int ii = i - s * 1280;
                const int n  = ii / 20, c = ii - n * 20;
                const char* src = (s ? wtl : wth) + n * 1600 + ky * 320 + c * 16;
                char* dst = smem + 46080 + s * 21504 + n * 336 + c * 16;
                *(uint4*)dst = *(const uint4*)src;
            }
            __syncthreads();

            const unsigned arow = ((my + ky) * 12 + mx) * 80;
            for (int kx = 0; kx < 5; kx++) {
                const unsigned ao = arow + kx * 80 + khalf;
                #pragma unroll
                for (int hf = 0; hf < 2; hf++) {
                    const unsigned ab = ao + hf * 32;
                    unsigned ah0, ah1, ah2, ah3, al0, al1, al2, al3;
                    ldsm4(ah0, ah1, ah2, ah3, aH + ab);
                    ldsm4(al0, al1, al2, al3, aL + ab);

                    const unsigned kb = (unsigned)(kx * 2 + hf) * 32;
                    unsigned bh[16], bl[16];
                    ldsm4(bh[0],  bh[1],  bh[2],  bh[3],  BH + l * 336 + kb);
                    ldsm4(bh[4],  bh[5],  bh[6],  bh[7],  BH + (l + 32) * 336 + kb);
                    ldsm4(bh[8],  bh[9],  bh[10], bh[11], BH + l * 336 + kb + 16);
                    ldsm4(bh[12], bh[13], bh[14], bh[15], BH + (l + 32) * 336 + kb + 16);
                    ldsm4(bl[0],  bl[1],  bl[2],  bl[3],  BL + l * 336 + kb);
                    ldsm4(bl[4],  bl[5],  bl[6],  bl[7],  BL + (l + 32) * 336 + kb);
                    ldsm4(bl[8],  bl[9],  bl[10], bl[11], BL + l * 336 + kb + 16);
                    ldsm4(bl[12], bl[13], bl[14], bl[15], BL + (l + 32) * 336 + kb + 16);

                    #pragma unroll
                    for (int j = 0; j < 8; j++) {
                        mma_bf16(acc[j], ah0, ah1, ah2, ah3, bh[j], bh[8 + j]);
                        mma_bf16(acc[j], ah0, ah1, ah2, ah3, bl[j], bl[8 + j]);
                        mma_bf16(acc[j], al0, al1, al2, al3, bh[j], bh[8 + j]);
                    }
                }
            }
        }

        // epilogue: 2x2 maxpool + bias + relu -> emb1 (fp32 + bf16 hi/lo)
        const long row_img = (long)blockIdx.x * 2 + img;
        #pragma unroll
        for (int j = 0; j < 8; j++) {
            float v0 = fmaxf(acc[j][0], acc[j][2]);
            float v1 = fmaxf(acc[j][1], acc[j][3]);
            const float u0 = fmaxf(v0, __shfl_down_sync(0xffffffffu, v0, 4));
            const float u1 = fmaxf(v1, __shfl_down_sync(0xffffffffu, v1, 4));
            if (((l >> 2) & 1) == 0) {
                const int pc = l >> 3;
                const int p  = mt * 4 + pc;
                const int nn = j * 8 + 2 * (l & 3);
                float2 o;
                o.x = fmaxf(u0 + b2[nn], 0.f);
                o.y = fmaxf(u1 + b2[nn + 1], 0.f);
                const long base = row_img * DIM + p * 64 + nn;
                *(float2*)&g_emb1[base] = o;
                const __nv_bfloat16 h0 = __float2bfloat16(o.x);
                const __nv_bfloat16 h1 = __float2bfloat16(o.y);
                __nv_bfloat162 hh; hh.x = h0; hh.y = h1;
                __nv_bfloat162 ll;
                ll.x = __float2bfloat16(o.x - __bfloat162float(h0));
                ll.y = __float2bfloat16(o.y - __bfloat162float(h1));
                *(__nv_bfloat162*)&g_emb1h[base] = hh;
                *(__nv_bfloat162*)&g_emb1l[base] = ll;
            }
        }
    }
}

// ---------------------------------------------------------------------------
// Tensor-core attention: s = sigmoid(tanh(emb @ W + b) @ v + vb)
// CTA = 64 rows x 256 att units; 8 warps = 4 m-tiles x 2 n-halves.
// A,B staged hi/lo in smem, 144B row stride (conflict-free ldmatrix).
// smem: Ah@0(9216) Al@9216 Bh@18432(36864) Bl@55296 sb@92160 sv@93184 wred@94208
// ---------------------------------------------------------------------------
#define ATT_SMEM 94720

__global__ __launch_bounds__(256) void att_mma_kernel(
    int lvl, const float* __restrict__ b, const float* __restrict__ v,
    const float* __restrict__ vb)
{
    extern __shared__ char sm[];
    const unsigned sb32 = (unsigned)__cvta_generic_to_shared(sm);
    const int tid = threadIdx.x;
    const int row0 = blockIdx.x * 64;

    const __nv_bfloat16* eh = lvl == 0 ? g_emb1h : (lvl == 1 ? g_emb2h : g_emb3h);
    const __nv_bfloat16* el = lvl == 0 ? g_emb1l : (lvl == 1 ? g_emb2l : g_emb3l);
    const __nv_bfloat16* wh = g_awt_hi + (size_t)lvl * (NATT * DIM);
    const __nv_bfloat16* wl = g_awt_lo + (size_t)lvl * (NATT * DIM);
    float* s_out = s_buf(lvl);

    float* sbf  = (float*)(sm + 92160);
    float* svf  = (float*)(sm + 93184);
    float* wred = (float*)(sm + 94208);
    sbf[tid] = b[tid];
    svf[tid] = v[tid];

    const int l  = tid & 31, w = tid >> 5;
    const int mt = w & 3, nh = w >> 2;
    const int lane_r = ((l >> 3) & 1) * 8 + (l & 7);
    const unsigned khalf = ((l >> 4) & 1) * 16;

    float acc[16][4];
    #pragma unroll
    for (int j = 0; j < 16; j++)
        #pragma unroll
        for (int q = 0; q < 4; q++) acc[j][q] = 0.f;

    for (int kc = 0; kc < 16; kc++) {
        __syncthreads();
        const int k0 = kc * 64;
        // stage A: 64 rows x 64 k, hi+lo (1024 uint4)
        for (int i = tid; i < 1024; i += 256) {
            const int pl = i >> 9, ii = i & 511;
            const int r = ii >> 3, c = ii & 7;
            const __nv_bfloat16* src =
                (pl ? el : eh) + (size_t)(row0 + r) * DIM + k0 + c * 8;
            *(uint4*)(sm + pl * 9216 + r * 144 + c * 16) = *(const uint4*)src;
        }
        // stage B: 256 n x 64 k, hi+lo (4096 uint4)
        for (int i = tid; i < 4096; i += 256) {
            const int pl = i >> 11, ii = i & 2047;
            const int n = ii >> 3, c = ii & 7;
            const __nv_bfloat16* src =
                (pl ? wl : wh) + (size_t)n * DIM + k0 + c * 8;
            *(uint4*)(sm + 18432 + pl * 36864 + n * 144 + c * 16) = *(const uint4*)src;
        }
        __syncthreads();

        #pragma unroll
        for (int ks = 0; ks < 4; ks++) {
            const unsigned aoff = (unsigned)(mt * 16 + lane_r) * 144 + ks * 32 + khalf;
            unsigned ah0, ah1, ah2, ah3, al0, al1, al2, al3;
            ldsm4(ah0, ah1, ah2, ah3, sb32 + aoff);
            ldsm4(al0, al1, al2, al3, sb32 + 9216 + aoff);
            #pragma unroll
            for (int g = 0; g < 4; g++) {
                const unsigned boff = (unsigned)(nh * 128 + g * 32 + l) * 144 + ks * 32;
                unsigned b0h[4], b1h[4], b0l[4], b1l[4];
                ldsm4(b0h[0], b0h[1], b0h[2], b0h[3], sb32 + 18432 + boff);
                ldsm4(b1h[0], b1h[1], b1h[2], b1h[3], sb32 + 18432 + boff + 16);
                ldsm4(b0l[0], b0l[1], b0l[2], b0l[3], sb32 + 55296 + boff);
                ldsm4(b1l[0], b1l[1], b1l[2], b1l[3], sb32 + 55296 + boff + 16);
                #pragma unroll
                for (int jj = 0; jj < 4; jj++) {
                    float* c = acc[g * 4 + jj];
                    mma_bf16(c, ah0, ah1, ah2, ah3, b0h[jj], b1h[jj]);
                    mma_bf16(c, ah0, ah1, ah2, ah3, b0l[jj], b1l[jj]);
                    mma_bf16(c, al0, al1, al2, al3, b0h[jj], b1h[jj]);
                }
            }
        }
    }

    // epilogue: tanh(h+b)*v, reduce over n -> per-row score
    float pvA = 0.f, pvB = 0.f;
    #pragma unroll
    for (int j = 0; j < 16; j++) {
        const int n = nh * 128 + j * 8 + (l & 3) * 2;
        const float b0v = sbf[n], b1v = sbf[n + 1];
        const float v0 = svf[n], v1 = svf[n + 1];
        pvA += tanhf(acc[j][0] + b0v) * v0 + tanhf(acc[j][1] + b1v) * v1;
        pvB += tanhf(acc[j][2] + b0v) * v0 + tanhf(acc[j][3] + b1v) * v1;
    }
    pvA += __shfl_xor_sync(0xffffffffu, pvA, 1);
    pvA += __shfl_xor_sync(0xffffffffu, pvA, 2);
    pvB += __shfl_xor_sync(0xffffffffu, pvB, 1);
    pvB += __shfl_xor_sync(0xffffffffu, pvB, 2);
    if ((l & 3) == 0) {
        const int r = l >> 2;   // 0..7
        wred[(mt * 16 + r) * 2 + nh]     = pvA;
        wred[(mt * 16 + r + 8) * 2 + nh] = pvB;
    }
    __syncthreads();
    if (tid < 64) {
        const float z = wred[tid * 2] + wred[tid * 2 + 1] + vb[0];
        s_out[row0 + tid] = 1.f / (1.f + expf(-z));
    }
}

// ---------------------------------------------------------------------------
__global__ __launch_bounds__(1024) void stats_kernel(int lvl, int R)
{
    __shared__ float red[1024];
    const float* s = s_buf(lvl);
    const int tid = threadIdx.x;

    float m = -1e30f;
    for (int i = tid; i < R; i += 1024) m = fmaxf(m, s[i]);
    red[tid] = m; __syncthreads();
    for (int off = 512; off; off >>= 1) {
        if (tid < off) red[tid] = fmaxf(red[tid], red[tid + off]);
        __syncthreads();
    }
    const float mx = red[0];
    __syncthreads();

    float sum = 0.f;
    for (int i = tid; i < R; i += 1024) sum += expf(s[i] - mx);
    red[tid] = sum; __syncthreads();
    for (int off = 512; off; off >>= 1) {
        if (tid < off) red[tid] += red[tid + off];
        __syncthreads();
    }
    if (tid == 0) { g_stats[lvl * 2] = mx; g_stats[lvl * 2 + 1] = red[0]; }
}

// ---------------------------------------------------------------------------
// segsum: weighted bag pooling (fp32) + emit bf16 hi/lo for next attention
// ---------------------------------------------------------------------------
__global__ __launch_bounds__(256) void segsum_kernel(int lvl)
{
    __shared__ float ws[16];
    const float* ein  = emb_buf(lvl);
    float*       eout = emb_buf(lvl + 1);
    __nv_bfloat16* eouth = lvl == 0 ? g_emb2h : g_emb3h;
    __nv_bfloat16* eoutl = lvl == 0 ? g_emb2l : g_emb3l;
    const float* s    = s_buf(lvl);
    const int bg = blockIdx.x, tid = threadIdx.x;

    if (tid < 16) {
        const float mx = g_stats[lvl * 2];
        const float inv = 1.f / g_stats[lvl * 2 + 1];
        ws[tid] = expf(s[bg * 16 + tid] - mx) * inv;
    }
    __syncthreads();

    const float4* base = (const float4*)(ein + (long)bg * 16 * DIM);
    float4* dst = (float4*)(eout + (long)bg * DIM);
    for (int d = tid; d < DIM / 4; d += 256) {
        float4 a = make_float4(0.f, 0.f, 0.f, 0.f);
        #pragma unroll
        for (int i = 0; i < 16; i++) {
            const float w = ws[i];
            const float4 e = base[i * (DIM / 4) + d];
            a.x += w * e.x; a.y += w * e.y; a.z += w * e.z; a.w += w * e.w;
        }
        dst[d] = a;
        const long eb = (long)bg * DIM + d * 4;
        float av[4] = {a.x, a.y, a.z, a.w};
        #pragma unroll
        for (int q = 0; q < 4; q++) {
            const __nv_bfloat16 h = __float2bfloat16(av[q]);
            eouth[eb + q] = h;
            eoutl[eb + q] = __float2bfloat16(av[q] - __bfloat162float(h));
        }
    }
}

// ---------------------------------------------------------------------------
__global__ __launch_bounds__(512) void final_kernel(
    const float* __restrict__ clsW, const float* __restrict__ clsb,
    const float* __restrict__ outW, const float* __restrict__ outb,
    float* __restrict__ out)
{
    __shared__ float w3[64];
    __shared__ float outer[DIM];
    __shared__ float red[512];
    const int tid = threadIdx.x;
    const float* s3 = s_buf(2);

    if (tid == 0) {
        float mx = -1e30f;
        for (int i = 0; i < 64; i++) mx = fmaxf(mx, s3[i]);
        float sum = 0.f;
        for (int i = 0; i < 64; i++) { float e = expf(s3[i] - mx); w3[i] = e; sum += e; }
        const float inv = 1.f / sum;
        for (int i = 0; i < 64; i++) w3[i] *= inv;
    }
    __syncthreads();

    for (int d = tid; d < DIM; d += 512) {
        float acc = 0.f;
        #pragma unroll 8
        for (int b2 = 0; b2 < 64; b2++) acc += w3[b2] * g_emb3[b2 * DIM + d];
        outer[d] = acc;
    }
    __syncthreads();

    float acc = 0.f;
    const float* wp = clsW + tid;
    for (int d = 0; d < DIM; d++) acc += outer[d] * wp[d * NCLS];
    red[tid] = (acc + clsb[tid]) * outW[tid];
    __syncthreads();
    for (int off = 256; off; off >>= 1) {
        if (tid < off) red[tid] += red[tid + off];
        __syncthreads();
    }
    if (tid == 0) out[0] = 1.f / (1.f + expf(-(red[0] + outb[0])));
}

// ---------------------------------------------------------------------------
extern "C" void kernel_launch(void* const* d_in, const int* in_sizes, int n_in,
                              void* d_out, int out_size)
{
    const float* x    = (const float*)d_in[0];
    const float* c1w  = (const float*)d_in[1];
    const float* c1b  = (const float*)d_in[2];
    const float* c2w  = (const float*)d_in[3];
    const float* c2b  = (const float*)d_in[4];
    const float* a1W  = (const float*)d_in[5];
    const float* a1b  = (const float*)d_in[6];
    const float* a1v  = (const float*)d_in[7];
    const float* a1vb = (const float*)d_in[8];
    const float* a2W  = (const float*)d_in[9];
    const float* a2b  = (const float*)d_in[10];
    const float* a2v  = (const float*)d_in[11];
    const float* a2vb = (const float*)d_in[12];
    const float* a3W  = (const float*)d_in[13];
    const float* a3b  = (const float*)d_in[14];
    const float* a3v  = (const float*)d_in[15];
    const float* a3vb = (const float*)d_in[16];
    const float* clsW = (const float*)d_in[17];
    const float* clsb = (const float*)d_in[18];
    const float* outW = (const float*)d_in[19];
    const float* outb = (const float*)d_in[20];

    cudaFuncSetAttribute(fused_conv_kernel,
                         cudaFuncAttributeMaxDynamicSharedMemorySize, FC_SMEM);
    cudaFuncSetAttribute(att_mma_kernel,
                         cudaFuncAttributeMaxDynamicSharedMemorySize, ATT_SMEM);

    prep_w2t<<<200, 256>>>(c2w);
    prep_awt<<<1024, 256>>>(a1W, 0);
    prep_awt<<<1024, 256>>>(a2W, 1);
    prep_awt<<<1024, 256>>>(a3W, 2);

    fused_conv_kernel<<<N_INST / 2, 256, FC_SMEM>>>(x, c1w, c1b, c2b);

    att_mma_kernel<<<N_INST / 64, 256, ATT_SMEM>>>(0, a1b, a1v, a1vb);
    stats_kernel<<<1, 1024>>>(0, N_INST);
    segsum_kernel<<<NB1, 256>>>(0);

    att_mma_kernel<<<NB1 / 64, 256, ATT_SMEM>>>(1, a2b, a2v, a2vb);
    stats_kernel<<<1, 1024>>>(1, NB1);
    segsum_kernel<<<NB2, 256>>>(1);

    att_mma_kernel<<<NB2 / 64, 256, ATT_SMEM>>>(2, a3b, a3v, a3vb);
    final_kernel<<<1, 512>>>(clsW, clsb, outW, outb, (float*)d_out);
}